// round 1
// baseline (speedup 1.0000x reference)
#include <cuda_runtime.h>
#include <cstdint>

// ---------------------------------------------------------------------------
// SSIM + L1 fused loss, GB300 sm_103a
// X, Y: [32, 1, 1024, 1024] fp32.  w: 9x9 Gaussian (sigma=1.5) -- separable,
// taps hardcoded as compile-time constants (immediate-form FFMA).
// Output: scalar fp32 = 0.5 * mean(1 - SSIM_map) + 1.0 * mean(|X - Y|)
// ---------------------------------------------------------------------------

#define IW 1024
#define IH 1024
#define OW 1016
#define OH 1016
#define NIMG 32
#define TW 128
#define TH 32
#define HALO 8
#define THREADS 128
#define TILE_W (TW + HALO)   // 136
#define TILE_H (TH + HALO)   // 40

// exp(-c^2 / (2*1.5^2)) for c = 4,3,2,1,0 (double precision), normalized.
constexpr double E0 = 0.02856550;   // exp(-32/9)
constexpr double E1 = 0.13533528;   // exp(-2)
constexpr double E2 = 0.41111229;   // exp(-8/9)
constexpr double E3 = 0.80073740;   // exp(-2/9)
constexpr double GS = 1.0 + 2.0 * (E0 + E1 + E2 + E3);

__device__ constexpr float G[9] = {
    (float)(E0 / GS), (float)(E1 / GS), (float)(E2 / GS), (float)(E3 / GS),
    (float)(1.0 / GS),
    (float)(E3 / GS), (float)(E2 / GS), (float)(E1 / GS), (float)(E0 / GS)
};

__device__ double g_acc[2];  // [0] = sum(1 - S) over SSIM map, [1] = sum |x-y|

__global__ void ssim_init_kernel() {
    g_acc[0] = 0.0;
    g_acc[1] = 0.0;
}

__global__ __launch_bounds__(THREADS) void ssim_main_kernel(
    const float* __restrict__ X, const float* __restrict__ Y) {
    __shared__ float2 tile[TILE_H][TILE_W];  // (x, y) pairs, 43.5 KB

    const int tx  = blockIdx.x;   // 0..7   (column tiles of 128)
    const int ty  = blockIdx.y;   // 0..31  (row tiles of 32)
    const int img = blockIdx.z;   // 0..31
    const int ix0 = tx * TW;
    const int iy0 = ty * TH;
    const size_t base = (size_t)img * IW * IH;
    const float* __restrict__ Xi = X + base;
    const float* __restrict__ Yi = Y + base;
    const int tid = threadIdx.x;

    // ---- Load tile (with +8 halo right/bottom) and accumulate owned L1 ----
    float l1 = 0.f;
    #pragma unroll 4
    for (int idx = tid; idx < TILE_H * TILE_W; idx += THREADS) {
        int ly = idx / TILE_W;
        int lx = idx - ly * TILE_W;
        int gy = iy0 + ly;
        int gx = ix0 + lx;
        float xv = 0.f, yv = 0.f;
        if (gy < IH && gx < IW) {
            xv = Xi[(size_t)gy * IW + gx];
            yv = Yi[(size_t)gy * IW + gx];
        }
        tile[ly][lx] = make_float2(xv, yv);
        // L1 over the exclusive (non-halo) region: tiles exactly cover 1024^2
        if (ly < TH && lx < TW) l1 += fabsf(xv - yv);
    }
    __syncthreads();

    // ---- Separable conv: horizontal in SMEM, vertical output-stationary ----
    const int  lane     = tid;                  // output column within tile
    const bool colvalid = (ix0 + lane) < OW;
    const int  nrows    = (iy0 + TH <= OH) ? TH : (OH - iy0);

    float a0[9] = {}, a1[9] = {}, a2[9] = {}, a3[9] = {}, a4[9] = {};
    float ssim = 0.f;
    constexpr float C1 = 0.0004f;  // (0.01*2)^2
    constexpr float C2 = 0.0036f;  // (0.03*2)^2

    #pragma unroll
    for (int r = 0; r < TILE_H; ++r) {
        // Horizontal 9-tap conv at tile row r, 5 maps at once.
        float hx = 0.f, hy = 0.f, hxx = 0.f, hyy = 0.f, hxy = 0.f;
        #pragma unroll
        for (int k = 0; k < 9; ++k) {
            float2 v  = tile[r][lane + k];
            float  g  = G[k];
            float  gx = g * v.x;
            float  gy = g * v.y;
            hx  += gx;
            hy  += gy;
            hxx += gx * v.x;
            hyy += gy * v.y;
            hxy += gx * v.y;
        }
        // Scatter into vertical ring accumulators (indices constant-folded).
        #pragma unroll
        for (int j = 0; j < 9; ++j) {
            int o = r - j;
            if (o < 0 || o >= TH) continue;
            int s = o % 9;
            float g = G[j];
            a0[s] += g * hx;
            a1[s] += g * hy;
            a2[s] += g * hxx;
            a3[s] += g * hyy;
            a4[s] += g * hxy;
        }
        // Output row (r - 8) is complete.
        if (r >= HALO) {
            int o = r - HALO;
            int s = o % 9;
            float ux = a0[s], uy = a1[s], uxx = a2[s], uyy = a3[s], uxy = a4[s];
            a0[s] = 0.f; a1[s] = 0.f; a2[s] = 0.f; a3[s] = 0.f; a4[s] = 0.f;
            if (colvalid && (o < nrows)) {
                float vx  = uxx - ux * ux;
                float vy  = uyy - uy * uy;
                float vxy = uxy - ux * uy;
                float A1v = 2.f * ux * uy + C1;
                float A2v = 2.f * vxy + C2;
                float B1v = ux * ux + uy * uy + C1;
                float B2v = vx + vy + C2;
                float S   = __fdividef(A1v * A2v, B1v * B2v);
                ssim += (1.f - S);
            }
        }
    }

    // ---- Block reduction, one double atomic per block ----
    #pragma unroll
    for (int off = 16; off; off >>= 1) {
        ssim += __shfl_down_sync(0xffffffffu, ssim, off);
        l1   += __shfl_down_sync(0xffffffffu, l1,   off);
    }
    __shared__ float red[2][THREADS / 32];
    int w = tid >> 5;
    if ((tid & 31) == 0) { red[0][w] = ssim; red[1][w] = l1; }
    __syncthreads();
    if (tid == 0) {
        float s = 0.f, l = 0.f;
        #pragma unroll
        for (int i = 0; i < THREADS / 32; ++i) { s += red[0][i]; l += red[1][i]; }
        atomicAdd(&g_acc[0], (double)s);
        atomicAdd(&g_acc[1], (double)l);
    }
}

__global__ void ssim_finish_kernel(float* __restrict__ out) {
    double ssim_mean = g_acc[0] / ((double)NIMG * OW * OH);
    double l1_mean   = g_acc[1] / ((double)NIMG * IW * IH);
    out[0] = (float)(0.5 * ssim_mean + 1.0 * l1_mean);
}

extern "C" void kernel_launch(void* const* d_in, const int* in_sizes, int n_in,
                              void* d_out, int out_size) {
    const float* X = (const float*)d_in[0];
    const float* Y = (const float*)d_in[1];
    // d_in[2] is the 9x9 window; taps are hardcoded (mathematically identical,
    // separable form) so it is unused.
    (void)in_sizes; (void)n_in; (void)out_size;

    ssim_init_kernel<<<1, 1>>>();
    dim3 grid(IW / TW, IH / TH, NIMG);  // (8, 32, 32) = 8192 blocks
    ssim_main_kernel<<<grid, THREADS>>>(X, Y);
    ssim_finish_kernel<<<1, 1>>>((float*)d_out);
}